// round 14
// baseline (speedup 1.0000x reference)
#include <cuda_runtime.h>
#include <cstdint>

#define N_NODES 100000
#define N_EDGES 1600000
#define D 64
#define CAP 64
#define BN_EPS 1e-5f
#define ROWS 256
#define STR 67                   // hs stride (floats)
#define WSTR 68                  // weight smem stride
#define NBLK_MLP ((N_NODES + ROWS - 1) / ROWS)      // 391
#define GNPW 8
#define GROWS (8 * GNPW)
#define NBLK_G ((N_NODES + GROWS - 1) / GROWS)      // 1563

typedef unsigned long long ull;

#define FMA2(d,a,b,c) asm("fma.rn.f32x2 %0, %1, %2, %3;" : "=l"(d) : "l"(a), "l"(b), "l"(c))
#define ADD2(d,a,b)   asm("add.rn.f32x2 %0, %1, %2;"     : "=l"(d) : "l"(a), "l"(b))
#define PK2(d,lo,hi)  asm("mov.b64 %0, {%1, %2};"        : "=l"(d) : "f"(lo), "f"(hi))
#define UPK2(lo,hi,s) asm("mov.b64 {%0, %1}, %2;"        : "=f"(lo), "=f"(hi) : "l"(s))
#define CVT_TF32(o,i) asm("cvt.rna.tf32.f32 %0, %1;"     : "=r"(o) : "f"(i))
#define MMA_TF32(c0,c1,c2,c3,a0,a1,a2,a3,b0,b1) \
    asm volatile("mma.sync.aligned.m16n8k8.row.col.f32.tf32.tf32.f32 " \
                 "{%0,%1,%2,%3}, {%4,%5,%6,%7}, {%8,%9}, {%0,%1,%2,%3};" \
                 : "+f"(c0), "+f"(c1), "+f"(c2), "+f"(c3) \
                 : "r"(a0), "r"(a1), "r"(a2), "r"(a3), "r"(b0), "r"(b1))

// smem float layout
#define SM_HS   0
#define SM_W1   (ROWS * STR)                 // 17152
#define SM_W2   (SM_W1 + 64 * WSTR)          // +4352
#define SM_BS1  (SM_W2 + 64 * WSTR)
#define SM_BS2  (SM_BS1 + 64)
#define SM_RS   (SM_BS2 + 64)
#define SM_RQ   (SM_RS + 256)
#define SM_FLOATS (SM_RQ + 256)
#define SMEM_BYTES (SM_FLOATS * 4)           // ~106KB -> 2 CTAs/SM

// ---------------- scratch ----------------
__device__ float g_h [N_NODES * D];
__device__ float g_y [N_NODES * D];
__device__ int   g_deg[N_NODES];
__device__ int   g_srt[(size_t)N_NODES * CAP];
__device__ float g_sum[D];
__device__ float g_sq [D];

__global__ void k_zero()
{
    int i = blockIdx.x * blockDim.x + threadIdx.x;
    if (i < N_NODES) g_deg[i] = 0;
    if (i < D) { g_sum[i] = 0.f; g_sq[i] = 0.f; }
}

__global__ void k_bucket(const int* __restrict__ src, const int* __restrict__ dst)
{
    int e = blockIdx.x * blockDim.x + threadIdx.x;
    if (e >= N_EDGES) return;
    int d = dst[e];
    int p = atomicAdd(&g_deg[d], 1);
    if (p < CAP) g_srt[(size_t)d * CAP + p] = src[e];
}

// ---------------- gather (R12 version, unchanged) ----------------
__global__ __launch_bounds__(256) void k_gather(const ulonglong2* __restrict__ featp4,
                                                const float* __restrict__ eps)
{
    int tid  = threadIdx.x;
    int wid  = tid >> 5;
    int lane = tid & 31;
    int half = lane >> 4;
    int li   = lane & 15;
    const unsigned FULL = 0xffffffffu;

    int gnode0 = blockIdx.x * GROWS + wid * GNPW;
    if (gnode0 >= N_NODES) return;

    int dgl = 0;
    if (lane < GNPW) {
        int n = gnode0 + lane;
        if (n < N_NODES) dgl = g_deg[n];
    }

    ull se2;
    {
        float se = 1.0f + *eps;
        PK2(se2, se, se);
    }

    ulonglong2* gh4 = reinterpret_cast<ulonglong2*>(g_h);

    int4 pia, pib;
    {
        const int4* ip0 = reinterpret_cast<const int4*>(g_srt + (size_t)gnode0 * CAP);
        pia = ip0[0];
        pib = ip0[1];
    }

    #pragma unroll 1
    for (int rr = 0; rr < GNPW; rr++) {
        int node = gnode0 + rr;
        if (node >= N_NODES) break;

        int dg = __shfl_sync(FULL, dgl, rr);
        if (dg > CAP) dg = CAP;

        const int4* ip = reinterpret_cast<const int4*>(g_srt + (size_t)node * CAP);
        int4 ia = pia, ib = pib;

        if (rr < GNPW - 1 && node + 1 < N_NODES) {
            const int4* ipn = reinterpret_cast<const int4*>(g_srt + (size_t)(node + 1) * CAP);
            pia = ipn[0];
            pib = ipn[1];
        }

        ull ax = 0ull, ay = 0ull;

        int full = dg & ~7;
        #pragma unroll 1
        for (int j = 0; j < full; j += 8) {
            int4 na = ia, nb = ib;
            if (j + 8 < full) {
                na = ip[((j + 8) >> 2)];
                nb = ip[((j + 8) >> 2) + 1];
            }
            int s0 = half ? ia.y : ia.x;
            int s1 = half ? ia.w : ia.z;
            int s2 = half ? ib.y : ib.x;
            int s3 = half ? ib.w : ib.z;
            ulonglong2 v0 = featp4[(size_t)s0 * 16 + li];
            ulonglong2 v1 = featp4[(size_t)s1 * 16 + li];
            ulonglong2 v2 = featp4[(size_t)s2 * 16 + li];
            ulonglong2 v3 = featp4[(size_t)s3 * 16 + li];
            ull t0x, t0y, t1x, t1y, tx, ty;
            ADD2(t0x, v0.x, v1.x); ADD2(t0y, v0.y, v1.y);
            ADD2(t1x, v2.x, v3.x); ADD2(t1y, v2.y, v3.y);
            ADD2(tx, t0x, t1x);    ADD2(ty, t0y, t1y);
            ADD2(ax, ax, tx);      ADD2(ay, ay, ty);
            ia = na; ib = nb;
        }

        int rem = dg - full;
        if (rem) {
            int4 ja = ip[(full >> 2)];
            int4 jb = ip[(full >> 2) + 1];
            int s0 = half ? ja.y : ja.x;
            int s1 = half ? ja.w : ja.z;
            int s2 = half ? jb.y : jb.x;
            int s3 = half ? jb.w : jb.z;
            ulonglong2 v0 = featp4[(size_t)s0 * 16 + li];
            ulonglong2 v1 = featp4[(size_t)s1 * 16 + li];
            ulonglong2 v2 = featp4[(size_t)s2 * 16 + li];
            ulonglong2 v3 = featp4[(size_t)s3 * 16 + li];
            if (half + 0 >= rem) { v0.x = 0ull; v0.y = 0ull; }
            if (half + 2 >= rem) { v1.x = 0ull; v1.y = 0ull; }
            if (half + 4 >= rem) { v2.x = 0ull; v2.y = 0ull; }
            if (half + 6 >= rem) { v3.x = 0ull; v3.y = 0ull; }
            ull t0x, t0y, t1x, t1y, tx, ty;
            ADD2(t0x, v0.x, v1.x); ADD2(t0y, v0.y, v1.y);
            ADD2(t1x, v2.x, v3.x); ADD2(t1y, v2.y, v3.y);
            ADD2(tx, t0x, t1x);    ADD2(ty, t0y, t1y);
            ADD2(ax, ax, tx);      ADD2(ay, ay, ty);
        }

        float f0, f1, f2, f3;
        UPK2(f0, f1, ax);
        UPK2(f2, f3, ay);
        f0 += __shfl_xor_sync(FULL, f0, 16);
        f1 += __shfl_xor_sync(FULL, f1, 16);
        f2 += __shfl_xor_sync(FULL, f2, 16);
        f3 += __shfl_xor_sync(FULL, f3, 16);
        if (half == 0) {
            ulonglong2 sv = featp4[(size_t)node * 16 + li];
            ull px, py;
            PK2(px, f0, f1);
            PK2(py, f2, f3);
            ulonglong2 out;
            FMA2(out.x, se2, sv.x, px);
            FMA2(out.y, se2, sv.y, py);
            gh4[(size_t)node * 16 + li] = out;
        }
    }
}

// ---------------- MLP via mma.sync tf32 ----------------
// 8 warps; warp w owns rows [w*32, w*32+32): 2 m16-tiles x 8 n8-tiles x 8 k8-steps.
__global__ __launch_bounds__(256) void k_mlp(const float* __restrict__ W1,
                                             const float* __restrict__ b1,
                                             const float* __restrict__ W2,
                                             const float* __restrict__ b2)
{
    extern __shared__ float smem[];
    float*    hs  = smem + SM_HS;
    uint32_t* hsU = reinterpret_cast<uint32_t*>(hs);
    uint32_t* w1U = reinterpret_cast<uint32_t*>(smem + SM_W1);
    uint32_t* w2U = reinterpret_cast<uint32_t*>(smem + SM_W2);
    float* bs1 = smem + SM_BS1;
    float* bs2 = smem + SM_BS2;
    float* rsm = smem + SM_RS;
    float* rqm = smem + SM_RQ;

    int tid  = threadIdx.x;
    int base = blockIdx.x * ROWS;
    int w    = tid >> 5;
    int lane = tid & 31;
    int g    = lane >> 2;        // groupID (0..7)
    int tg   = lane & 3;         // threadID in group (0..3)
    int warpRow = w * 32;

    // stage weights (tf32) + biases
    for (int i = tid; i < 4096; i += 256) {
        int k = i >> 6, n = i & 63;
        uint32_t v1, v2;
        CVT_TF32(v1, W1[i]);
        CVT_TF32(v2, W2[i]);
        w1U[k * WSTR + n] = v1;
        w2U[k * WSTR + n] = v2;
    }
    if (tid < 64) { bs1[tid] = b1[tid]; bs2[tid] = b2[tid]; }

    // stage h tile (tf32 bit patterns into hsU)
    {
        const ull* gh = reinterpret_cast<const ull*>(g_h);
        for (int i = tid; i < ROWS * 32; i += 256) {
            int row = i >> 5;
            int c2  = i & 31;
            int gn  = base + row;
            ull v = (gn < N_NODES) ? gh[(size_t)gn * 32 + c2] : 0ull;
            float lo, hi;
            UPK2(lo, hi, v);
            uint32_t ulo, uhi;
            CVT_TF32(ulo, lo);
            CVT_TF32(uhi, hi);
            hsU[row * STR + 2*c2]     = ulo;
            hsU[row * STR + 2*c2 + 1] = uhi;
        }
    }
    __syncthreads();

    // ---- layer 1: C = h @ W1 ----
    float c1[2][8][4];
    #pragma unroll
    for (int mt = 0; mt < 2; mt++)
        #pragma unroll
        for (int nt = 0; nt < 8; nt++)
            #pragma unroll
            for (int q = 0; q < 4; q++) c1[mt][nt][q] = 0.f;

    #pragma unroll
    for (int kt = 0; kt < 8; kt++) {
        uint32_t a[2][4];
        #pragma unroll
        for (int mt = 0; mt < 2; mt++) {
            int r0 = warpRow + mt * 16 + g;
            a[mt][0] = hsU[r0 * STR + kt*8 + tg];
            a[mt][1] = hsU[(r0 + 8) * STR + kt*8 + tg];
            a[mt][2] = hsU[r0 * STR + kt*8 + tg + 4];
            a[mt][3] = hsU[(r0 + 8) * STR + kt*8 + tg + 4];
        }
        #pragma unroll
        for (int nt = 0; nt < 8; nt++) {
            uint32_t b0 = w1U[(kt*8 + tg) * WSTR + nt*8 + g];
            uint32_t b1r = w1U[(kt*8 + tg + 4) * WSTR + nt*8 + g];
            MMA_TF32(c1[0][nt][0], c1[0][nt][1], c1[0][nt][2], c1[0][nt][3],
                     a[0][0], a[0][1], a[0][2], a[0][3], b0, b1r);
            MMA_TF32(c1[1][nt][0], c1[1][nt][1], c1[1][nt][2], c1[1][nt][3],
                     a[1][0], a[1][1], a[1][2], a[1][3], b0, b1r);
        }
    }

    // +b1, relu, tf32 -> back into own rows (warp-local; no block sync needed)
    #pragma unroll
    for (int mt = 0; mt < 2; mt++) {
        int ra = warpRow + mt * 16 + g;
        int rb = ra + 8;
        #pragma unroll
        for (int nt = 0; nt < 8; nt++) {
            int ca = nt*8 + 2*tg;
            int cb = ca + 1;
            float f0 = fmaxf(c1[mt][nt][0] + bs1[ca], 0.f);
            float f1 = fmaxf(c1[mt][nt][1] + bs1[cb], 0.f);
            float f2 = fmaxf(c1[mt][nt][2] + bs1[ca], 0.f);
            float f3 = fmaxf(c1[mt][nt][3] + bs1[cb], 0.f);
            uint32_t u0, u1, u2, u3;
            CVT_TF32(u0, f0);
            CVT_TF32(u1, f1);
            CVT_TF32(u2, f2);
            CVT_TF32(u3, f3);
            hsU[ra * STR + ca] = u0;
            hsU[ra * STR + cb] = u1;
            hsU[rb * STR + ca] = u2;
            hsU[rb * STR + cb] = u3;
        }
    }
    __syncwarp();

    // ---- layer 2: C = t @ W2 ----
    float c2[2][8][4];
    #pragma unroll
    for (int mt = 0; mt < 2; mt++)
        #pragma unroll
        for (int nt = 0; nt < 8; nt++)
            #pragma unroll
            for (int q = 0; q < 4; q++) c2[mt][nt][q] = 0.f;

    #pragma unroll
    for (int kt = 0; kt < 8; kt++) {
        uint32_t a[2][4];
        #pragma unroll
        for (int mt = 0; mt < 2; mt++) {
            int r0 = warpRow + mt * 16 + g;
            a[mt][0] = hsU[r0 * STR + kt*8 + tg];
            a[mt][1] = hsU[(r0 + 8) * STR + kt*8 + tg];
            a[mt][2] = hsU[r0 * STR + kt*8 + tg + 4];
            a[mt][3] = hsU[(r0 + 8) * STR + kt*8 + tg + 4];
        }
        #pragma unroll
        for (int nt = 0; nt < 8; nt++) {
            uint32_t b0 = w2U[(kt*8 + tg) * WSTR + nt*8 + g];
            uint32_t b1r = w2U[(kt*8 + tg + 4) * WSTR + nt*8 + g];
            MMA_TF32(c2[0][nt][0], c2[0][nt][1], c2[0][nt][2], c2[0][nt][3],
                     a[0][0], a[0][1], a[0][2], a[0][3], b0, b1r);
            MMA_TF32(c2[1][nt][0], c2[1][nt][1], c2[1][nt][2], c2[1][nt][3],
                     a[1][0], a[1][1], a[1][2], a[1][3], b0, b1r);
        }
    }
    __syncwarp();

    // +b2, mask OOB rows, store f32 into hs for BN + writeback
    #pragma unroll
    for (int mt = 0; mt < 2; mt++) {
        int ra = warpRow + mt * 16 + g;
        int rb = ra + 8;
        bool va = (base + ra) < N_NODES;
        bool vb = (base + rb) < N_NODES;
        #pragma unroll
        for (int nt = 0; nt < 8; nt++) {
            int ca = nt*8 + 2*tg;
            int cb = ca + 1;
            hs[ra * STR + ca] = va ? (c2[mt][nt][0] + bs2[ca]) : 0.f;
            hs[ra * STR + cb] = va ? (c2[mt][nt][1] + bs2[cb]) : 0.f;
            hs[rb * STR + ca] = vb ? (c2[mt][nt][2] + bs2[ca]) : 0.f;
            hs[rb * STR + cb] = vb ? (c2[mt][nt][3] + bs2[cb]) : 0.f;
        }
    }
    __syncthreads();

    // BN stats: segmented column sums (stride-67, conflict-free)
    {
        int col = tid & 63;
        int seg = tid >> 6;
        const float* hp = hs + (seg * 64) * STR + col;
        float s = 0.f, q = 0.f;
        #pragma unroll 8
        for (int r2 = 0; r2 < 64; r2++) {
            float v = hp[r2 * STR];
            s += v;
            q = fmaf(v, v, q);
        }
        rsm[tid] = s;
        rqm[tid] = q;
    }
    __syncthreads();
    if (tid < 64) {
        atomicAdd(&g_sum[tid], rsm[tid] + rsm[64 + tid] + rsm[128 + tid] + rsm[192 + tid]);
        atomicAdd(&g_sq [tid], rqm[tid] + rqm[64 + tid] + rqm[128 + tid] + rqm[192 + tid]);
    }

    // y writeback (coalesced)
    for (int i = tid; i < ROWS * 32; i += 256) {
        int row = i >> 5;
        int c2  = i & 31;
        int gn  = base + row;
        if (gn < N_NODES) {
            float2 v = make_float2(hs[row * STR + 2*c2], hs[row * STR + 2*c2 + 1]);
            *reinterpret_cast<float2*>(g_y + (size_t)gn * D + 2*c2) = v;
        }
    }
}

// ---------------- epilogue (inline BN finalize) ----------------
__global__ __launch_bounds__(256) void k_epi(const float4* __restrict__ feat4,
                                             const float* __restrict__ gamma,
                                             const float* __restrict__ beta,
                                             float4* __restrict__ out4)
{
    __shared__ float4 s_scale[16], s_shift[16];
    int tid = threadIdx.x;
    if (tid < D) {
        float inv_n = 1.0f / (float)N_NODES;
        float mean = g_sum[tid] * inv_n;
        float var  = g_sq[tid] * inv_n - mean * mean;
        float sc   = gamma[tid] * rsqrtf(var + BN_EPS);
        float sh   = beta[tid] - mean * sc;
        reinterpret_cast<float*>(s_scale)[tid] = sc;
        reinterpret_cast<float*>(s_shift)[tid] = sh;
    }
    __syncthreads();

    const float4* y4 = reinterpret_cast<const float4*>(g_y);
    int total = N_NODES * 16;
    for (int i = blockIdx.x * blockDim.x + tid; i < total; i += gridDim.x * blockDim.x) {
        int c4 = i & 15;
        float4 y = y4[i];
        float4 s = s_scale[c4];
        float4 h = s_shift[c4];
        float4 f = feat4[i];
        float4 rr;
        rr.x = f.x + fmaxf(fmaf(y.x, s.x, h.x), 0.f);
        rr.y = f.y + fmaxf(fmaf(y.y, s.y, h.y), 0.f);
        rr.z = f.z + fmaxf(fmaf(y.z, s.z, h.z), 0.f);
        rr.w = f.w + fmaxf(fmaf(y.w, s.w, h.w), 0.f);
        out4[i] = rr;
    }
}

extern "C" void kernel_launch(void* const* d_in, const int* in_sizes, int n_in,
                              void* d_out, int out_size)
{
    const float*  feat  = (const float*)d_in[0];
    const int*    src   = (const int*)  d_in[1];
    const int*    dst   = (const int*)  d_in[2];
    const float*  eps   = (const float*)d_in[3];
    const float*  W1    = (const float*)d_in[4];
    const float*  b1    = (const float*)d_in[5];
    const float*  W2    = (const float*)d_in[6];
    const float*  b2    = (const float*)d_in[7];
    const float*  gamma = (const float*)d_in[8];
    const float*  beta  = (const float*)d_in[9];
    float4* out4 = (float4*)d_out;

    static bool attr_done = false;
    if (!attr_done) {
        cudaFuncSetAttribute(k_mlp, cudaFuncAttributeMaxDynamicSharedMemorySize, SMEM_BYTES);
        attr_done = true;
    }

    k_zero  <<<(N_NODES + 255) / 256, 256>>>();                           // idx 0
    k_bucket<<<(N_EDGES + 255) / 256, 256>>>(src, dst);                   // idx 1
    k_gather<<<NBLK_G, 256>>>((const ulonglong2*)feat, eps);              // idx 2
    k_mlp   <<<NBLK_MLP, 256, SMEM_BYTES>>>(W1, b1, W2, b2);              // idx 3 (profiled)
    k_epi   <<<1184, 256>>>((const float4*)feat, gamma, beta, out4);      // idx 4
}

// round 15
// speedup vs baseline: 1.0761x; 1.0761x over previous
#include <cuda_runtime.h>
#include <cstdint>

#define N_NODES 100000
#define N_EDGES 1600000
#define D 64
#define CAP 64
#define BN_EPS 1e-5f
#define ROWS 256
#define STR 67
#define NTILES ((N_NODES + ROWS - 1) / ROWS)        // 391
#define MLP_GRID 296                                 // 2 CTAs/SM x 148 SMs
#define GNPW 8
#define GROWS (8 * GNPW)
#define NBLK_G ((N_NODES + GROWS - 1) / GROWS)      // 1563

typedef unsigned long long ull;

#define FMA2(d,a,b,c) asm("fma.rn.f32x2 %0, %1, %2, %3;" : "=l"(d) : "l"(a), "l"(b), "l"(c))
#define ADD2(d,a,b)   asm("add.rn.f32x2 %0, %1, %2;"     : "=l"(d) : "l"(a), "l"(b))
#define PK2(d,lo,hi)  asm("mov.b64 %0, {%1, %2};"        : "=l"(d) : "f"(lo), "f"(hi))
#define UPK2(lo,hi,s) asm("mov.b64 {%0, %1}, %2;"        : "=f"(lo), "=f"(hi) : "l"(s))

// MLP smem layout (floats)
#define SM_HS   0
#define SM_WS   (ROWS * STR)
#define SM_BS1  (SM_WS + 8192)
#define SM_BS2  (SM_BS1 + 64)
#define SM_RS   (SM_BS2 + 64)
#define SM_RQ   (SM_RS + 256)
#define SM_FLOATS (SM_RQ + 256)
#define SMEM_BYTES (SM_FLOATS * 4)

// ---------------- scratch ----------------
__device__ float g_h [N_NODES * D];
__device__ float g_y [N_NODES * D];
__device__ int   g_deg[N_NODES];
__device__ int   g_srt[(size_t)N_NODES * CAP];
__device__ float g_sum[D];
__device__ float g_sq [D];
__device__ int   g_tile;

__global__ void k_zero()
{
    int i = blockIdx.x * blockDim.x + threadIdx.x;
    if (i < N_NODES) g_deg[i] = 0;
    if (i < D) { g_sum[i] = 0.f; g_sq[i] = 0.f; }
    if (i == 64) g_tile = 0;
}

__global__ void k_bucket(const int* __restrict__ src, const int* __restrict__ dst)
{
    int e = blockIdx.x * blockDim.x + threadIdx.x;
    if (e >= N_EDGES) return;
    int d = dst[e];
    int p = atomicAdd(&g_deg[d], 1);
    if (p < CAP) g_srt[(size_t)d * CAP + p] = src[e];
}

// ---------------- gather (R12 version, unchanged) ----------------
__global__ __launch_bounds__(256) void k_gather(const ulonglong2* __restrict__ featp4,
                                                const float* __restrict__ eps)
{
    int tid  = threadIdx.x;
    int wid  = tid >> 5;
    int lane = tid & 31;
    int half = lane >> 4;
    int li   = lane & 15;
    const unsigned FULL = 0xffffffffu;

    int gnode0 = blockIdx.x * GROWS + wid * GNPW;
    if (gnode0 >= N_NODES) return;

    int dgl = 0;
    if (lane < GNPW) {
        int n = gnode0 + lane;
        if (n < N_NODES) dgl = g_deg[n];
    }

    ull se2;
    {
        float se = 1.0f + *eps;
        PK2(se2, se, se);
    }

    ulonglong2* gh4 = reinterpret_cast<ulonglong2*>(g_h);

    int4 pia, pib;
    {
        const int4* ip0 = reinterpret_cast<const int4*>(g_srt + (size_t)gnode0 * CAP);
        pia = ip0[0];
        pib = ip0[1];
    }

    #pragma unroll 1
    for (int rr = 0; rr < GNPW; rr++) {
        int node = gnode0 + rr;
        if (node >= N_NODES) break;

        int dg = __shfl_sync(FULL, dgl, rr);
        if (dg > CAP) dg = CAP;

        const int4* ip = reinterpret_cast<const int4*>(g_srt + (size_t)node * CAP);
        int4 ia = pia, ib = pib;

        if (rr < GNPW - 1 && node + 1 < N_NODES) {
            const int4* ipn = reinterpret_cast<const int4*>(g_srt + (size_t)(node + 1) * CAP);
            pia = ipn[0];
            pib = ipn[1];
        }

        ull ax = 0ull, ay = 0ull;

        int full = dg & ~7;
        #pragma unroll 1
        for (int j = 0; j < full; j += 8) {
            int4 na = ia, nb = ib;
            if (j + 8 < full) {
                na = ip[((j + 8) >> 2)];
                nb = ip[((j + 8) >> 2) + 1];
            }
            int s0 = half ? ia.y : ia.x;
            int s1 = half ? ia.w : ia.z;
            int s2 = half ? ib.y : ib.x;
            int s3 = half ? ib.w : ib.z;
            ulonglong2 v0 = featp4[(size_t)s0 * 16 + li];
            ulonglong2 v1 = featp4[(size_t)s1 * 16 + li];
            ulonglong2 v2 = featp4[(size_t)s2 * 16 + li];
            ulonglong2 v3 = featp4[(size_t)s3 * 16 + li];
            ull t0x, t0y, t1x, t1y, tx, ty;
            ADD2(t0x, v0.x, v1.x); ADD2(t0y, v0.y, v1.y);
            ADD2(t1x, v2.x, v3.x); ADD2(t1y, v2.y, v3.y);
            ADD2(tx, t0x, t1x);    ADD2(ty, t0y, t1y);
            ADD2(ax, ax, tx);      ADD2(ay, ay, ty);
            ia = na; ib = nb;
        }

        int rem = dg - full;
        if (rem) {
            int4 ja = ip[(full >> 2)];
            int4 jb = ip[(full >> 2) + 1];
            int s0 = half ? ja.y : ja.x;
            int s1 = half ? ja.w : ja.z;
            int s2 = half ? jb.y : jb.x;
            int s3 = half ? jb.w : jb.z;
            ulonglong2 v0 = featp4[(size_t)s0 * 16 + li];
            ulonglong2 v1 = featp4[(size_t)s1 * 16 + li];
            ulonglong2 v2 = featp4[(size_t)s2 * 16 + li];
            ulonglong2 v3 = featp4[(size_t)s3 * 16 + li];
            if (half + 0 >= rem) { v0.x = 0ull; v0.y = 0ull; }
            if (half + 2 >= rem) { v1.x = 0ull; v1.y = 0ull; }
            if (half + 4 >= rem) { v2.x = 0ull; v2.y = 0ull; }
            if (half + 6 >= rem) { v3.x = 0ull; v3.y = 0ull; }
            ull t0x, t0y, t1x, t1y, tx, ty;
            ADD2(t0x, v0.x, v1.x); ADD2(t0y, v0.y, v1.y);
            ADD2(t1x, v2.x, v3.x); ADD2(t1y, v2.y, v3.y);
            ADD2(tx, t0x, t1x);    ADD2(ty, t0y, t1y);
            ADD2(ax, ax, tx);      ADD2(ay, ay, ty);
        }

        float f0, f1, f2, f3;
        UPK2(f0, f1, ax);
        UPK2(f2, f3, ay);
        f0 += __shfl_xor_sync(FULL, f0, 16);
        f1 += __shfl_xor_sync(FULL, f1, 16);
        f2 += __shfl_xor_sync(FULL, f2, 16);
        f3 += __shfl_xor_sync(FULL, f3, 16);
        if (half == 0) {
            ulonglong2 sv = featp4[(size_t)node * 16 + li];
            ull px, py;
            PK2(px, f0, f1);
            PK2(py, f2, f3);
            ulonglong2 out;
            FMA2(out.x, se2, sv.x, px);
            FMA2(out.y, se2, sv.y, py);
            gh4[(size_t)node * 16 + li] = out;
        }
    }
}

// ---------------- MLP: persistent work-stealing, 4 rows x 16 cols/thread ----------------
__global__ __launch_bounds__(256) void k_mlp(const float* __restrict__ W1,
                                             const float* __restrict__ b1,
                                             const float* __restrict__ W2,
                                             const float* __restrict__ b2)
{
    extern __shared__ float smem[];
    float* hs  = smem + SM_HS;
    float* ws  = smem + SM_WS;
    float* bs1 = smem + SM_BS1;
    float* bs2 = smem + SM_BS2;
    float* rsm = smem + SM_RS;
    float* rqm = smem + SM_RQ;
    __shared__ int s_tile;

    int tid  = threadIdx.x;
    int rg   = tid & 63;
    int colq = tid >> 6;
    int c0   = colq * 16;

    // weights + biases loaded ONCE per block
    for (int i = tid; i < 4096; i += 256) ws[i]        = W1[i];
    for (int i = tid; i < 4096; i += 256) ws[4096 + i] = W2[i];
    if (tid < 64) { bs1[tid] = b1[tid]; bs2[tid] = b2[tid]; }

    #pragma unroll 1
    while (true) {
        if (tid == 0) s_tile = atomicAdd(&g_tile, 1);
        __syncthreads();                 // also guards hs reuse from prev iter
        int tile = s_tile;
        if (tile >= NTILES) return;
        int base = tile * ROWS;

        // stage h tile
        {
            const ull* gh = reinterpret_cast<const ull*>(g_h);
            for (int i = tid; i < ROWS * 32; i += 256) {
                int row = i >> 5;
                int c2  = i & 31;
                int gn  = base + row;
                ull v = (gn < N_NODES) ? gh[(size_t)gn * 32 + c2] : 0ull;
                float lo, hi;
                UPK2(lo, hi, v);
                hs[row * STR + 2*c2]     = lo;
                hs[row * STR + 2*c2 + 1] = hi;
            }
        }
        __syncthreads();

        // ---- layer 1 ----
        ull t2[4][8];
        #pragma unroll
        for (int s = 0; s < 4; s++)
            #pragma unroll
            for (int j = 0; j < 8; j++)
                PK2(t2[s][j], bs1[c0 + 2*j], bs1[c0 + 2*j + 1]);

        #pragma unroll 4
        for (int k = 0; k < 64; k++) {
            ull hv2[4];
            #pragma unroll
            for (int s = 0; s < 4; s++) {
                float hv = hs[(rg + 64*s) * STR + k];
                PK2(hv2[s], hv, hv);
            }
            const ulonglong2* wp = reinterpret_cast<const ulonglong2*>(ws + (k << 6) + c0);
            #pragma unroll
            for (int m = 0; m < 4; m++) {
                ulonglong2 w = wp[m];
                #pragma unroll
                for (int s = 0; s < 4; s++) {
                    FMA2(t2[s][2*m],     hv2[s], w.x, t2[s][2*m]);
                    FMA2(t2[s][2*m + 1], hv2[s], w.y, t2[s][2*m + 1]);
                }
            }
        }
        __syncthreads();
        #pragma unroll
        for (int s = 0; s < 4; s++) {
            float* hp = hs + (rg + 64*s) * STR + c0;
            #pragma unroll
            for (int j = 0; j < 8; j++) {
                float lo, hi;
                UPK2(lo, hi, t2[s][j]);
                hp[2*j]     = fmaxf(lo, 0.f);
                hp[2*j + 1] = fmaxf(hi, 0.f);
            }
        }
        __syncthreads();

        // ---- layer 2 ----
        ull o2[4][8];
        #pragma unroll
        for (int s = 0; s < 4; s++)
            #pragma unroll
            for (int j = 0; j < 8; j++)
                PK2(o2[s][j], bs2[c0 + 2*j], bs2[c0 + 2*j + 1]);

        #pragma unroll 4
        for (int k = 0; k < 64; k++) {
            ull hv2[4];
            #pragma unroll
            for (int s = 0; s < 4; s++) {
                float hv = hs[(rg + 64*s) * STR + k];
                PK2(hv2[s], hv, hv);
            }
            const ulonglong2* wp = reinterpret_cast<const ulonglong2*>(ws + 4096 + (k << 6) + c0);
            #pragma unroll
            for (int m = 0; m < 4; m++) {
                ulonglong2 w = wp[m];
                #pragma unroll
                for (int s = 0; s < 4; s++) {
                    FMA2(o2[s][2*m],     hv2[s], w.x, o2[s][2*m]);
                    FMA2(o2[s][2*m + 1], hv2[s], w.y, o2[s][2*m + 1]);
                }
            }
        }
        __syncthreads();

        #pragma unroll
        for (int s = 0; s < 4; s++) {
            int row = rg + 64*s;
            float* hp = hs + row * STR + c0;
            bool valid = (base + row) < N_NODES;
            #pragma unroll
            for (int j = 0; j < 8; j++) {
                float lo, hi;
                UPK2(lo, hi, o2[s][j]);
                hp[2*j]     = valid ? lo : 0.f;
                hp[2*j + 1] = valid ? hi : 0.f;
            }
        }
        __syncthreads();

        // BN stats: segmented column sums
        {
            int col = tid & 63;
            int seg = tid >> 6;
            const float* hp = hs + (seg * 64) * STR + col;
            float s = 0.f, q = 0.f;
            #pragma unroll 8
            for (int r2 = 0; r2 < 64; r2++) {
                float v = hp[r2 * STR];
                s += v;
                q = fmaf(v, v, q);
            }
            rsm[tid] = s;
            rqm[tid] = q;
        }
        __syncthreads();
        if (tid < 64) {
            atomicAdd(&g_sum[tid], rsm[tid] + rsm[64 + tid] + rsm[128 + tid] + rsm[192 + tid]);
            atomicAdd(&g_sq [tid], rqm[tid] + rqm[64 + tid] + rqm[128 + tid] + rqm[192 + tid]);
        }

        // y writeback (coalesced)
        for (int i = tid; i < ROWS * 32; i += 256) {
            int row = i >> 5;
            int c2  = i & 31;
            int gn  = base + row;
            if (gn < N_NODES) {
                float2 v = make_float2(hs[row * STR + 2*c2], hs[row * STR + 2*c2 + 1]);
                *reinterpret_cast<float2*>(g_y + (size_t)gn * D + 2*c2) = v;
            }
        }
    }
}

// ---------------- epilogue (inline BN finalize) ----------------
__global__ __launch_bounds__(256) void k_epi(const float4* __restrict__ feat4,
                                             const float* __restrict__ gamma,
                                             const float* __restrict__ beta,
                                             float4* __restrict__ out4)
{
    __shared__ float4 s_scale[16], s_shift[16];
    int tid = threadIdx.x;
    if (tid < D) {
        float inv_n = 1.0f / (float)N_NODES;
        float mean = g_sum[tid] * inv_n;
        float var  = g_sq[tid] * inv_n - mean * mean;
        float sc   = gamma[tid] * rsqrtf(var + BN_EPS);
        float sh   = beta[tid] - mean * sc;
        reinterpret_cast<float*>(s_scale)[tid] = sc;
        reinterpret_cast<float*>(s_shift)[tid] = sh;
    }
    __syncthreads();

    const float4* y4 = reinterpret_cast<const float4*>(g_y);
    int total = N_NODES * 16;
    for (int i = blockIdx.x * blockDim.x + tid; i < total; i += gridDim.x * blockDim.x) {
        int c4 = i & 15;
        float4 y = y4[i];
        float4 s = s_scale[c4];
        float4 h = s_shift[c4];
        float4 f = feat4[i];
        float4 rr;
        rr.x = f.x + fmaxf(fmaf(y.x, s.x, h.x), 0.f);
        rr.y = f.y + fmaxf(fmaf(y.y, s.y, h.y), 0.f);
        rr.z = f.z + fmaxf(fmaf(y.z, s.z, h.z), 0.f);
        rr.w = f.w + fmaxf(fmaf(y.w, s.w, h.w), 0.f);
        out4[i] = rr;
    }
}

extern "C" void kernel_launch(void* const* d_in, const int* in_sizes, int n_in,
                              void* d_out, int out_size)
{
    const float*  feat  = (const float*)d_in[0];
    const int*    src   = (const int*)  d_in[1];
    const int*    dst   = (const int*)  d_in[2];
    const float*  eps   = (const float*)d_in[3];
    const float*  W1    = (const float*)d_in[4];
    const float*  b1    = (const float*)d_in[5];
    const float*  W2    = (const float*)d_in[6];
    const float*  b2    = (const float*)d_in[7];
    const float*  gamma = (const float*)d_in[8];
    const float*  beta  = (const float*)d_in[9];
    float4* out4 = (float4*)d_out;

    static bool attr_done = false;
    if (!attr_done) {
        cudaFuncSetAttribute(k_mlp, cudaFuncAttributeMaxDynamicSharedMemorySize, SMEM_BYTES);
        attr_done = true;
    }

    k_zero  <<<(N_NODES + 255) / 256, 256>>>();                           // idx 0
    k_bucket<<<(N_EDGES + 255) / 256, 256>>>(src, dst);                   // idx 1
    k_gather<<<NBLK_G, 256>>>((const ulonglong2*)feat, eps);              // idx 2
    k_mlp   <<<MLP_GRID, 256, SMEM_BYTES>>>(W1, b1, W2, b2);              // idx 3 (profiled)
    k_epi   <<<1184, 256>>>((const float4*)feat, gamma, beta, out4);      // idx 4
}

// round 16
// speedup vs baseline: 1.2006x; 1.1157x over previous
#include <cuda_runtime.h>
#include <cstdint>

#define N_NODES 100000
#define N_EDGES 1600000
#define D 64
#define CAP 64
#define BN_EPS 1e-5f
#define ROWS 256
#define STR 67
#define NTILES ((N_NODES + ROWS - 1) / ROWS)        // 391
#define MLP_GRID 296                                 // 2 CTAs/SM x 148 SMs
#define GNPW 8
#define GROWS (8 * GNPW)
#define NBLK_G ((N_NODES + GROWS - 1) / GROWS)      // 1563

typedef unsigned long long ull;

#define FMA2(d,a,b,c) asm("fma.rn.f32x2 %0, %1, %2, %3;" : "=l"(d) : "l"(a), "l"(b), "l"(c))
#define ADD2(d,a,b)   asm("add.rn.f32x2 %0, %1, %2;"     : "=l"(d) : "l"(a), "l"(b))
#define PK2(d,lo,hi)  asm("mov.b64 %0, {%1, %2};"        : "=l"(d) : "f"(lo), "f"(hi))
#define UPK2(lo,hi,s) asm("mov.b64 {%0, %1}, %2;"        : "=f"(lo), "=f"(hi) : "l"(s))

// MLP smem layout (floats)
#define SM_HS   0
#define SM_WS   (ROWS * STR)
#define SM_BS1  (SM_WS + 8192)
#define SM_BS2  (SM_BS1 + 64)
#define SM_RS   (SM_BS2 + 64)
#define SM_RQ   (SM_RS + 256)
#define SM_FLOATS (SM_RQ + 256)
#define SMEM_BYTES (SM_FLOATS * 4)

// ---------------- scratch ----------------
__device__ float g_h [N_NODES * D];
__device__ float g_y [N_NODES * D];
__device__ int   g_deg[N_NODES];
__device__ int   g_srt[(size_t)N_NODES * CAP];
__device__ float g_sum[D];
__device__ float g_sq [D];
__device__ int   g_tile;

__global__ void k_zero()
{
    int i = blockIdx.x * blockDim.x + threadIdx.x;
    if (i < N_NODES) g_deg[i] = 0;
    if (i < D) { g_sum[i] = 0.f; g_sq[i] = 0.f; }
    if (i == 64) g_tile = 0;
}

__global__ void k_bucket(const int* __restrict__ src, const int* __restrict__ dst)
{
    int e = blockIdx.x * blockDim.x + threadIdx.x;
    if (e >= N_EDGES) return;
    int d = dst[e];
    int p = atomicAdd(&g_deg[d], 1);
    if (p < CAP) g_srt[(size_t)d * CAP + p] = src[e];
}

// ---------------- gather (R12 version, unchanged) ----------------
__global__ __launch_bounds__(256) void k_gather(const ulonglong2* __restrict__ featp4,
                                                const float* __restrict__ eps)
{
    int tid  = threadIdx.x;
    int wid  = tid >> 5;
    int lane = tid & 31;
    int half = lane >> 4;
    int li   = lane & 15;
    const unsigned FULL = 0xffffffffu;

    int gnode0 = blockIdx.x * GROWS + wid * GNPW;
    if (gnode0 >= N_NODES) return;

    int dgl = 0;
    if (lane < GNPW) {
        int n = gnode0 + lane;
        if (n < N_NODES) dgl = g_deg[n];
    }

    ull se2;
    {
        float se = 1.0f + *eps;
        PK2(se2, se, se);
    }

    ulonglong2* gh4 = reinterpret_cast<ulonglong2*>(g_h);

    int4 pia, pib;
    {
        const int4* ip0 = reinterpret_cast<const int4*>(g_srt + (size_t)gnode0 * CAP);
        pia = ip0[0];
        pib = ip0[1];
    }

    #pragma unroll 1
    for (int rr = 0; rr < GNPW; rr++) {
        int node = gnode0 + rr;
        if (node >= N_NODES) break;

        int dg = __shfl_sync(FULL, dgl, rr);
        if (dg > CAP) dg = CAP;

        const int4* ip = reinterpret_cast<const int4*>(g_srt + (size_t)node * CAP);
        int4 ia = pia, ib = pib;

        if (rr < GNPW - 1 && node + 1 < N_NODES) {
            const int4* ipn = reinterpret_cast<const int4*>(g_srt + (size_t)(node + 1) * CAP);
            pia = ipn[0];
            pib = ipn[1];
        }

        ull ax = 0ull, ay = 0ull;

        int full = dg & ~7;
        #pragma unroll 1
        for (int j = 0; j < full; j += 8) {
            int4 na = ia, nb = ib;
            if (j + 8 < full) {
                na = ip[((j + 8) >> 2)];
                nb = ip[((j + 8) >> 2) + 1];
            }
            int s0 = half ? ia.y : ia.x;
            int s1 = half ? ia.w : ia.z;
            int s2 = half ? ib.y : ib.x;
            int s3 = half ? ib.w : ib.z;
            ulonglong2 v0 = featp4[(size_t)s0 * 16 + li];
            ulonglong2 v1 = featp4[(size_t)s1 * 16 + li];
            ulonglong2 v2 = featp4[(size_t)s2 * 16 + li];
            ulonglong2 v3 = featp4[(size_t)s3 * 16 + li];
            ull t0x, t0y, t1x, t1y, tx, ty;
            ADD2(t0x, v0.x, v1.x); ADD2(t0y, v0.y, v1.y);
            ADD2(t1x, v2.x, v3.x); ADD2(t1y, v2.y, v3.y);
            ADD2(tx, t0x, t1x);    ADD2(ty, t0y, t1y);
            ADD2(ax, ax, tx);      ADD2(ay, ay, ty);
            ia = na; ib = nb;
        }

        int rem = dg - full;
        if (rem) {
            int4 ja = ip[(full >> 2)];
            int4 jb = ip[(full >> 2) + 1];
            int s0 = half ? ja.y : ja.x;
            int s1 = half ? ja.w : ja.z;
            int s2 = half ? jb.y : jb.x;
            int s3 = half ? jb.w : jb.z;
            ulonglong2 v0 = featp4[(size_t)s0 * 16 + li];
            ulonglong2 v1 = featp4[(size_t)s1 * 16 + li];
            ulonglong2 v2 = featp4[(size_t)s2 * 16 + li];
            ulonglong2 v3 = featp4[(size_t)s3 * 16 + li];
            if (half + 0 >= rem) { v0.x = 0ull; v0.y = 0ull; }
            if (half + 2 >= rem) { v1.x = 0ull; v1.y = 0ull; }
            if (half + 4 >= rem) { v2.x = 0ull; v2.y = 0ull; }
            if (half + 6 >= rem) { v3.x = 0ull; v3.y = 0ull; }
            ull t0x, t0y, t1x, t1y, tx, ty;
            ADD2(t0x, v0.x, v1.x); ADD2(t0y, v0.y, v1.y);
            ADD2(t1x, v2.x, v3.x); ADD2(t1y, v2.y, v3.y);
            ADD2(tx, t0x, t1x);    ADD2(ty, t0y, t1y);
            ADD2(ax, ax, tx);      ADD2(ay, ay, ty);
        }

        float f0, f1, f2, f3;
        UPK2(f0, f1, ax);
        UPK2(f2, f3, ay);
        f0 += __shfl_xor_sync(FULL, f0, 16);
        f1 += __shfl_xor_sync(FULL, f1, 16);
        f2 += __shfl_xor_sync(FULL, f2, 16);
        f3 += __shfl_xor_sync(FULL, f3, 16);
        if (half == 0) {
            ulonglong2 sv = featp4[(size_t)node * 16 + li];
            ull px, py;
            PK2(px, f0, f1);
            PK2(py, f2, f3);
            ulonglong2 out;
            FMA2(out.x, se2, sv.x, px);
            FMA2(out.y, se2, sv.y, py);
            gh4[(size_t)node * 16 + li] = out;
        }
    }
}

// ---------------- MLP: persistent work-stealing, 4 rows x 16 cols/thread ----------------
__global__ __launch_bounds__(256) void k_mlp(const float* __restrict__ W1,
                                             const float* __restrict__ b1,
                                             const float* __restrict__ W2,
                                             const float* __restrict__ b2)
{
    extern __shared__ float smem[];
    float* hs  = smem + SM_HS;
    float* ws  = smem + SM_WS;
    float* bs1 = smem + SM_BS1;
    float* bs2 = smem + SM_BS2;
    float* rsm = smem + SM_RS;
    float* rqm = smem + SM_RQ;
    __shared__ int s_tile;

    int tid  = threadIdx.x;
    int rg   = tid & 63;
    int colq = tid >> 6;
    int c0   = colq * 16;

    // weights + biases loaded ONCE per block
    for (int i = tid; i < 4096; i += 256) ws[i]        = W1[i];
    for (int i = tid; i < 4096; i += 256) ws[4096 + i] = W2[i];
    if (tid < 64) { bs1[tid] = b1[tid]; bs2[tid] = b2[tid]; }

    #pragma unroll 1
    while (true) {
        if (tid == 0) s_tile = atomicAdd(&g_tile, 1);
        __syncthreads();                 // also guards hs reuse from prev iter
        int tile = s_tile;
        if (tile >= NTILES) return;
        int base = tile * ROWS;

        // stage h tile
        {
            const ull* gh = reinterpret_cast<const ull*>(g_h);
            for (int i = tid; i < ROWS * 32; i += 256) {
                int row = i >> 5;
                int c2  = i & 31;
                int gn  = base + row;
                ull v = (gn < N_NODES) ? gh[(size_t)gn * 32 + c2] : 0ull;
                float lo, hi;
                UPK2(lo, hi, v);
                hs[row * STR + 2*c2]     = lo;
                hs[row * STR + 2*c2 + 1] = hi;
            }
        }
        __syncthreads();

        // ---- layer 1 ----
        ull t2[4][8];
        #pragma unroll
        for (int s = 0; s < 4; s++)
            #pragma unroll
            for (int j = 0; j < 8; j++)
                PK2(t2[s][j], bs1[c0 + 2*j], bs1[c0 + 2*j + 1]);

        #pragma unroll 4
        for (int k = 0; k < 64; k++) {
            ull hv2[4];
            #pragma unroll
            for (int s = 0; s < 4; s++) {
                float hv = hs[(rg + 64*s) * STR + k];
                PK2(hv2[s], hv, hv);
            }
            const ulonglong2* wp = reinterpret_cast<const ulonglong2*>(ws + (k << 6) + c0);
            #pragma unroll
            for (int m = 0; m < 4; m++) {
                ulonglong2 w = wp[m];
                #pragma unroll
                for (int s = 0; s < 4; s++) {
                    FMA2(t2[s][2*m],     hv2[s], w.x, t2[s][2*m]);
                    FMA2(t2[s][2*m + 1], hv2[s], w.y, t2[s][2*m + 1]);
                }
            }
        }
        __syncthreads();
        #pragma unroll
        for (int s = 0; s < 4; s++) {
            float* hp = hs + (rg + 64*s) * STR + c0;
            #pragma unroll
            for (int j = 0; j < 8; j++) {
                float lo, hi;
                UPK2(lo, hi, t2[s][j]);
                hp[2*j]     = fmaxf(lo, 0.f);
                hp[2*j + 1] = fmaxf(hi, 0.f);
            }
        }
        __syncthreads();

        // ---- layer 2 ----
        ull o2[4][8];
        #pragma unroll
        for (int s = 0; s < 4; s++)
            #pragma unroll
            for (int j = 0; j < 8; j++)
                PK2(o2[s][j], bs2[c0 + 2*j], bs2[c0 + 2*j + 1]);

        #pragma unroll 4
        for (int k = 0; k < 64; k++) {
            ull hv2[4];
            #pragma unroll
            for (int s = 0; s < 4; s++) {
                float hv = hs[(rg + 64*s) * STR + k];
                PK2(hv2[s], hv, hv);
            }
            const ulonglong2* wp = reinterpret_cast<const ulonglong2*>(ws + 4096 + (k << 6) + c0);
            #pragma unroll
            for (int m = 0; m < 4; m++) {
                ulonglong2 w = wp[m];
                #pragma unroll
                for (int s = 0; s < 4; s++) {
                    FMA2(o2[s][2*m],     hv2[s], w.x, o2[s][2*m]);
                    FMA2(o2[s][2*m + 1], hv2[s], w.y, o2[s][2*m + 1]);
                }
            }
        }
        __syncthreads();

        #pragma unroll
        for (int s = 0; s < 4; s++) {
            int row = rg + 64*s;
            float* hp = hs + row * STR + c0;
            bool valid = (base + row) < N_NODES;
            #pragma unroll
            for (int j = 0; j < 8; j++) {
                float lo, hi;
                UPK2(lo, hi, o2[s][j]);
                hp[2*j]     = valid ? lo : 0.f;
                hp[2*j + 1] = valid ? hi : 0.f;
            }
        }
        __syncthreads();

        // BN stats: segmented column sums
        {
            int col = tid & 63;
            int seg = tid >> 6;
            const float* hp = hs + (seg * 64) * STR + col;
            float s = 0.f, q = 0.f;
            #pragma unroll 8
            for (int r2 = 0; r2 < 64; r2++) {
                float v = hp[r2 * STR];
                s += v;
                q = fmaf(v, v, q);
            }
            rsm[tid] = s;
            rqm[tid] = q;
        }
        __syncthreads();
        if (tid < 64) {
            atomicAdd(&g_sum[tid], rsm[tid] + rsm[64 + tid] + rsm[128 + tid] + rsm[192 + tid]);
            atomicAdd(&g_sq [tid], rqm[tid] + rqm[64 + tid] + rqm[128 + tid] + rqm[192 + tid]);
        }

        // y writeback (coalesced)
        for (int i = tid; i < ROWS * 32; i += 256) {
            int row = i >> 5;
            int c2  = i & 31;
            int gn  = base + row;
            if (gn < N_NODES) {
                float2 v = make_float2(hs[row * STR + 2*c2], hs[row * STR + 2*c2 + 1]);
                *reinterpret_cast<float2*>(g_y + (size_t)gn * D + 2*c2) = v;
            }
        }
    }
}

// ---------------- epilogue (inline BN finalize) ----------------
__global__ __launch_bounds__(256) void k_epi(const float4* __restrict__ feat4,
                                             const float* __restrict__ gamma,
                                             const float* __restrict__ beta,
                                             float4* __restrict__ out4)
{
    __shared__ float4 s_scale[16], s_shift[16];
    int tid = threadIdx.x;
    if (tid < D) {
        float inv_n = 1.0f / (float)N_NODES;
        float mean = g_sum[tid] * inv_n;
        float var  = g_sq[tid] * inv_n - mean * mean;
        float sc   = gamma[tid] * rsqrtf(var + BN_EPS);
        float sh   = beta[tid] - mean * sc;
        reinterpret_cast<float*>(s_scale)[tid] = sc;
        reinterpret_cast<float*>(s_shift)[tid] = sh;
    }
    __syncthreads();

    const float4* y4 = reinterpret_cast<const float4*>(g_y);
    int total = N_NODES * 16;
    for (int i = blockIdx.x * blockDim.x + tid; i < total; i += gridDim.x * blockDim.x) {
        int c4 = i & 15;
        float4 y = y4[i];
        float4 s = s_scale[c4];
        float4 h = s_shift[c4];
        float4 f = feat4[i];
        float4 rr;
        rr.x = f.x + fmaxf(fmaf(y.x, s.x, h.x), 0.f);
        rr.y = f.y + fmaxf(fmaf(y.y, s.y, h.y), 0.f);
        rr.z = f.z + fmaxf(fmaf(y.z, s.z, h.z), 0.f);
        rr.w = f.w + fmaxf(fmaf(y.w, s.w, h.w), 0.f);
        out4[i] = rr;
    }
}

extern "C" void kernel_launch(void* const* d_in, const int* in_sizes, int n_in,
                              void* d_out, int out_size)
{
    const float*  feat  = (const float*)d_in[0];
    const int*    src   = (const int*)  d_in[1];
    const int*    dst   = (const int*)  d_in[2];
    const float*  eps   = (const float*)d_in[3];
    const float*  W1    = (const float*)d_in[4];
    const float*  b1    = (const float*)d_in[5];
    const float*  W2    = (const float*)d_in[6];
    const float*  b2    = (const float*)d_in[7];
    const float*  gamma = (const float*)d_in[8];
    const float*  beta  = (const float*)d_in[9];
    float4* out4 = (float4*)d_out;

    static bool attr_done = false;
    if (!attr_done) {
        cudaFuncSetAttribute(k_mlp, cudaFuncAttributeMaxDynamicSharedMemorySize, SMEM_BYTES);
        attr_done = true;
    }

    k_zero  <<<(N_NODES + 255) / 256, 256>>>();                           // idx 0
    k_bucket<<<(N_EDGES + 255) / 256, 256>>>(src, dst);                   // idx 1
    k_gather<<<NBLK_G, 256>>>((const ulonglong2*)feat, eps);              // idx 2
    k_mlp   <<<MLP_GRID, 256, SMEM_BYTES>>>(W1, b1, W2, b2);              // idx 3 (profiled)
    k_epi   <<<1184, 256>>>((const float4*)feat, gamma, beta, out4);      // idx 4
}